// round 12
// baseline (speedup 1.0000x reference)
#include <cuda_runtime.h>
#include <cuda_bf16.h>
#include <cstdint>

#define BB 16
#define NN 1024
#define DD 128
#define BN (BB*NN)

// ---------------- scratch (device globals) ----------------
__device__ float         g_M2[DD*DD];                  // Ww^T @ A
__device__ float         g_b2[DD];                     // Wb @ A
__device__ __nv_bfloat16 g_u1[(size_t)BN*256];         // [t|h] hi
__device__ __nv_bfloat16 g_u2[(size_t)BN*256];         // [t|h] lo
__device__ __nv_bfloat16 g_v1[(size_t)BN*256];         // [h|t] hi
__device__ __nv_bfloat16 g_v2[(size_t)BN*256];         // [h|t] lo
__device__ __nv_bfloat16 g_hT1[(size_t)BB*DD*NN];      // hT[b][d][j] hi
__device__ __nv_bfloat16 g_hT2[(size_t)BB*DD*NN];      // lo
__device__ __nv_bfloat16 g_hS1[(size_t)BB*DD*NN];      // rden-scaled hT hi
__device__ __nv_bfloat16 g_hS2[(size_t)BB*DD*NN];      // lo
__device__ __nv_bfloat16 g_P1[(size_t)BB*NN*NN];       // 32 MB exp(scores) hi (0 if masked)
__device__ __nv_bfloat16 g_P2[(size_t)BB*NN*NN];       // 32 MB lo
__device__ float         g_dpart[BB*8*NN];             // column-sum partials per row-tile

// ---------------- helpers ----------------
__device__ __forceinline__ uint32_t smem_u32(const void* p) {
    uint32_t a;
    asm("{ .reg .u64 t; cvta.to.shared.u64 t, %1; cvt.u32.u64 %0, t; }" : "=r"(a) : "l"(p));
    return a;
}
__device__ __forceinline__ void ldsm4(uint32_t* r, uint32_t addr) {
    asm volatile("ldmatrix.sync.aligned.m8n8.x4.shared.b16 {%0,%1,%2,%3}, [%4];"
                 : "=r"(r[0]), "=r"(r[1]), "=r"(r[2]), "=r"(r[3]) : "r"(addr));
}
__device__ __forceinline__ void mma16816(float* c, const uint32_t* a, const uint32_t* b) {
    asm volatile("mma.sync.aligned.m16n8k16.row.col.f32.bf16.bf16.f32 "
                 "{%0,%1,%2,%3}, {%4,%5,%6,%7}, {%8,%9}, {%0,%1,%2,%3};"
                 : "+f"(c[0]), "+f"(c[1]), "+f"(c[2]), "+f"(c[3])
                 : "r"(a[0]), "r"(a[1]), "r"(a[2]), "r"(a[3]), "r"(b[0]), "r"(b[1]));
}
#define CP_ASYNC16(dst, src) \
    asm volatile("cp.async.cg.shared.global [%0], [%1], 16;" :: "r"(dst), "l"(src) : "memory")
#define CP_COMMIT() asm volatile("cp.async.commit_group;" ::: "memory")
#define CP_WAIT0()  asm volatile("cp.async.wait_group 0;" ::: "memory")

#define LDO 72            // bf16 elems per smem row (64 data + 8 pad)
#define MATB (128*LDO*2)  // 18432 bytes per staged 128x64 matrix
#define MATB64 (64*LDO*2) // 9216 bytes per staged 64x64 matrix
#define TSTR 129          // float stride for transpose staging (scalar access only)

__device__ __forceinline__ void split2(float v, __nv_bfloat16& hi, __nv_bfloat16& lo) {
    hi = __float2bfloat16_rn(v);
    lo = __float2bfloat16_rn(v - __bfloat162float(hi));
}

// ---------------------------------------------------------------------------
// prep: M2 = Ww^T @ A,  b2 = Wb @ A
// ---------------------------------------------------------------------------
__global__ void prep_M2_kernel(const float* __restrict__ Ww,
                               const float* __restrict__ Wb,
                               const float* __restrict__ A) {
    __shared__ float As[128 * 8];
    const int tid = threadIdx.x;
    const int l0 = blockIdx.x * 8;
#pragma unroll
    for (int q = 0; q < 4; q++) {
        int idx = tid + q * 256;
        int d = idx >> 3, l = idx & 7;
        As[d * 8 + l] = A[d * 128 + l0 + l];
    }
    __syncthreads();
    const int f = tid & 127, g = tid >> 7;
    float s[4] = {0.f, 0.f, 0.f, 0.f};
    for (int d = 0; d < 128; d++) {
        float w = Ww[d * 128 + f];
#pragma unroll
        for (int q = 0; q < 4; q++)
            s[q] += w * As[d * 8 + g * 4 + q];
    }
    *(float4*)&g_M2[f * 128 + l0 + g * 4] = make_float4(s[0], s[1], s[2], s[3]);
    if (tid < 8) {
        float sb2 = 0.f;
        for (int d = 0; d < 128; d++)
            sb2 += Wb[d] * As[d * 8 + tid];
        g_b2[l0 + tid] = sb2;
    }
}

// ---------------------------------------------------------------------------
// fused GEMM: path 0: h = x@Ww^T + Wb -> u[:,128:256], v[:,0:128], hT splits
//             path 1: t = x@M2   + b2 -> u[:,0:128],   v[:,128:256]
// ---------------------------------------------------------------------------
template<int LDA, int LDB>
__device__ __forceinline__ void mm8x8x4(const float* As, const float* Bs,
                                        int r0, int c0, int l, float acc[8][8]) {
    float a[8][4], bb[4][8];
#pragma unroll
    for (int i = 0; i < 8; i++) {
        float4 v = *(const float4*)&As[(r0 + i) * LDA + l];
        a[i][0]=v.x; a[i][1]=v.y; a[i][2]=v.z; a[i][3]=v.w;
    }
#pragma unroll
    for (int q = 0; q < 4; q++) {
        float4 v0 = *(const float4*)&Bs[(l + q) * LDB + c0];
        float4 v1 = *(const float4*)&Bs[(l + q) * LDB + c0 + 4];
        bb[q][0]=v0.x; bb[q][1]=v0.y; bb[q][2]=v0.z; bb[q][3]=v0.w;
        bb[q][4]=v1.x; bb[q][5]=v1.y; bb[q][6]=v1.z; bb[q][7]=v1.w;
    }
#pragma unroll
    for (int q = 0; q < 4; q++)
#pragma unroll
        for (int i = 0; i < 8; i++)
#pragma unroll
            for (int j = 0; j < 8; j++)
                acc[i][j] += a[i][q] * bb[q][j];
}

__global__ void __launch_bounds__(256, 1)
gemmht_kernel(const float* __restrict__ x, const float* __restrict__ Ww,
              const float* __restrict__ Wb) {
    extern __shared__ float smemf[];
    float* As = smemf;
    float* Bs = smemf + 128 * 128;
    const int tid = threadIdx.x;
    const int m0 = blockIdx.x * 128;
    const int path = blockIdx.y;

    const float4* Ag = (const float4*)(x + (size_t)m0 * 128);
#pragma unroll
    for (int it = 0; it < 16; it++)
        ((float4*)As)[tid + it * 256] = Ag[tid + it * 256];
    if (path == 0) {
#pragma unroll
        for (int it = 0; it < 16; it++) {
            int lin = tid + it * 256;
            int c = lin & 127, k4 = lin >> 7;
            float4 v = ((const float4*)Ww)[c * 32 + k4];
            Bs[(4*k4+0)*128+c]=v.x; Bs[(4*k4+1)*128+c]=v.y;
            Bs[(4*k4+2)*128+c]=v.z; Bs[(4*k4+3)*128+c]=v.w;
        }
    } else {
#pragma unroll
        for (int it = 0; it < 16; it++)
            ((float4*)Bs)[tid + it * 256] = ((const float4*)g_M2)[tid + it * 256];
    }
    __syncthreads();
    const int r0 = (tid >> 4) * 8, c0 = (tid & 15) * 8;
    float acc[8][8] = {};
#pragma unroll
    for (int l = 0; l < 128; l += 4)
        mm8x8x4<128, 128>(As, Bs, r0, c0, l, acc);

    const float* bias = path ? g_b2 : Wb;
    float bv[8];
#pragma unroll
    for (int j = 0; j < 8; j++) bv[j] = bias[c0 + j];
#pragma unroll
    for (int i = 0; i < 8; i++)
#pragma unroll
        for (int j = 0; j < 8; j++)
            acc[i][j] += bv[j];

#pragma unroll
    for (int i = 0; i < 8; i++) {
        int node = m0 + r0 + i;
        __nv_bfloat16 hi[8], lo[8];
#pragma unroll
        for (int j = 0; j < 8; j++) split2(acc[i][j], hi[j], lo[j]);
        size_t bu = (size_t)node * 256 + c0 + (path ? 0 : 128);
        size_t bvv = (size_t)node * 256 + c0 + (path ? 128 : 0);
        *(uint4*)&g_u1[bu]  = *(uint4*)hi;
        *(uint4*)&g_u2[bu]  = *(uint4*)lo;
        *(uint4*)&g_v1[bvv] = *(uint4*)hi;
        *(uint4*)&g_v2[bvv] = *(uint4*)lo;
    }

    if (path == 0) {
        __syncthreads();
        float* Ts = smemf;   // [128][TSTR], scalar access
#pragma unroll
        for (int i = 0; i < 8; i++)
#pragma unroll
            for (int j = 0; j < 8; j++)
                Ts[(r0 + i) * TSTR + c0 + j] = acc[i][j];
        __syncthreads();
        const int bb_ = m0 >> 10, j0 = m0 & 1023;
#pragma unroll
        for (int it = 0; it < 32; it++) {
            int idx = it * 256 + tid;
            int d = idx >> 6, jp = idx & 63;
            float v0 = Ts[(2 * jp) * TSTR + d];
            float v1 = Ts[(2 * jp + 1) * TSTR + d];
            __nv_bfloat16 h0, l0_, h1, l1;
            split2(v0, h0, l0_);
            split2(v1, h1, l1);
            size_t o = ((size_t)bb_ * DD + d) * NN + j0 + 2 * jp;
            *(uint32_t*)&g_hT1[o] = (uint32_t)__bfloat16_as_ushort(h0) |
                                    ((uint32_t)__bfloat16_as_ushort(h1) << 16);
            *(uint32_t*)&g_hT2[o] = (uint32_t)__bfloat16_as_ushort(l0_) |
                                    ((uint32_t)__bfloat16_as_ushort(l1) << 16);
        }
    }
}

// ---------------------------------------------------------------------------
// warp-mma core (M=128), fragment reuse: (a1b1, a2b1) then (a1b2)
// ---------------------------------------------------------------------------
__device__ __forceinline__ void mma_block(uint32_t base, int mrow, int ncol,
                                          int lane, float* acc) {
    const uint32_t A1 = base, A2 = base + MATB;
    const uint32_t B1 = base + 2 * MATB, B2 = base + 3 * MATB;
    const int lg = lane >> 3, lr = lane & 7;
#pragma unroll
    for (int ks = 0; ks < 4; ks++) {
        const int kk = ks * 16;
        uint32_t a1f[2][4], a2f[2][4];
#pragma unroll
        for (int mi = 0; mi < 2; mi++) {
            uint32_t ro = ((mrow + mi*16 + (lane & 15)) * LDO + kk + (lane >> 4) * 8) * 2;
            ldsm4(a1f[mi], A1 + ro);
            ldsm4(a2f[mi], A2 + ro);
        }
        uint32_t bf[4][4];
#pragma unroll
        for (int nb = 0; nb < 4; nb++) {
            int n = ncol + nb * 16 + (lg >> 1) * 8 + lr;
            ldsm4(bf[nb], B1 + (n * LDO + kk + (lg & 1) * 8) * 2);
        }
#pragma unroll
        for (int mi = 0; mi < 2; mi++)
#pragma unroll
            for (int ni = 0; ni < 8; ni++) {
                mma16816(&acc[(mi*8+ni)*4], a1f[mi], &bf[ni>>1][(ni&1)*2]);
                mma16816(&acc[(mi*8+ni)*4], a2f[mi], &bf[ni>>1][(ni&1)*2]);
            }
#pragma unroll
        for (int nb = 0; nb < 4; nb++) {
            int n = ncol + nb * 16 + (lg >> 1) * 8 + lr;
            ldsm4(bf[nb], B2 + (n * LDO + kk + (lg & 1) * 8) * 2);
        }
#pragma unroll
        for (int mi = 0; mi < 2; mi++)
#pragma unroll
            for (int ni = 0; ni < 8; ni++)
                mma16816(&acc[(mi*8+ni)*4], a1f[mi], &bf[ni>>1][(ni&1)*2]);
    }
}

// ---------------------------------------------------------------------------
// K3: scores. grid (36 pairs, 16 b), 256 thr, 2 CTA/SM.
// P1/P2 = bf16 split of (adj>0 ? exp(e) : 0); colsum partials include +1 for masked
// ---------------------------------------------------------------------------
#define SC_SMEM (4*MATB)   // 73728; epilogue: Ts[128][129] (66048) + red (4096)

__global__ void __launch_bounds__(256, 2)
scores_mma_kernel(const float* __restrict__ adj) {
    extern __shared__ char smem[];
    const uint32_t sb = smem_u32(smem);
    float* Ts = (float*)smem;
    float* red = (float*)(smem + 66048);

    const int tid = threadIdx.x;
    const int wid = tid >> 5, lane = tid & 31;
    const int b = blockIdx.y;
    int p = blockIdx.x, jT = 0;
    while (p >= 8 - jT) { p -= 8 - jT; jT++; }
    const int kT = jT + p;

    const int mrow = (wid >> 1) * 32, ncol = (wid & 1) * 64;
    float acc[64];
#pragma unroll
    for (int i = 0; i < 64; i++) acc[i] = 0.f;

    const __nv_bfloat16* srcs[4] = { g_u1, g_u2, g_v1, g_v2 };
    const int nb0[4] = { jT * 128, jT * 128, kT * 128, kT * 128 };

#pragma unroll
    for (int chunk = 0; chunk < 4; chunk++) {
        const int k0 = chunk * 64;
        if (chunk) __syncthreads();
#pragma unroll
        for (int m = 0; m < 4; m++) {
            const __nv_bfloat16* src = srcs[m];
            uint32_t smb = sb + m * MATB;
#pragma unroll
            for (int it = 0; it < 4; it++) {
                int row = it * 32 + (tid >> 3), f8 = tid & 7;
                const void* g = &src[((size_t)(b * NN + nb0[m] + row)) * 256 + k0 + f8 * 8];
                CP_ASYNC16(smb + row * (LDO*2) + f8 * 16, g);
            }
        }
        CP_COMMIT();
        CP_WAIT0();
        __syncthreads();
        mma_block(sb, mrow, ncol, lane, acc);
    }

    __syncthreads();
#pragma unroll
    for (int mi = 0; mi < 2; mi++)
#pragma unroll
        for (int ni = 0; ni < 8; ni++) {
            int row = mrow + mi*16 + (lane >> 2);
            int col = ncol + ni*8 + (lane & 3) * 2;
            float* c = &acc[(mi*8+ni)*4];
            Ts[row * TSTR + col]           = c[0];
            Ts[row * TSTR + col + 1]       = c[1];
            Ts[(row + 8) * TSTR + col]     = c[2];
            Ts[(row + 8) * TSTR + col + 1] = c[3];
        }
    __syncthreads();

    const float* adjb = adj + (size_t)b * NN * NN;
    const int a = tid >> 5, c4 = tid & 31;

    // direct tile (jT rows, kT cols): P splits + column partial sums
    float cs[4] = {0.f, 0.f, 0.f, 0.f};
#pragma unroll
    for (int it = 0; it < 16; it++) {
        int rr = a + 8 * it;
        int jg = jT * 128 + rr, kg = kT * 128 + 4 * c4;
        float4 av = *(const float4*)&adjb[(size_t)jg * NN + kg];
        const float* tr = &Ts[rr * TSTR + 4 * c4];
        float pv[4];
        pv[0] = (av.x > 0.f) ? __expf(tr[0]) : 0.f;
        pv[1] = (av.y > 0.f) ? __expf(tr[1]) : 0.f;
        pv[2] = (av.z > 0.f) ? __expf(tr[2]) : 0.f;
        pv[3] = (av.w > 0.f) ? __expf(tr[3]) : 0.f;
        cs[0] += (av.x > 0.f) ? pv[0] : 1.f;   // masked contributes exp(0)=1
        cs[1] += (av.y > 0.f) ? pv[1] : 1.f;
        cs[2] += (av.z > 0.f) ? pv[2] : 1.f;
        cs[3] += (av.w > 0.f) ? pv[3] : 1.f;
        __nv_bfloat16 h4[4], l4[4];
#pragma unroll
        for (int q = 0; q < 4; q++) split2(pv[q], h4[q], l4[q]);
        size_t o = (size_t)b * NN * NN + (size_t)jg * NN + kg;
        *(uint2*)&g_P1[o] = *(uint2*)h4;
        *(uint2*)&g_P2[o] = *(uint2*)l4;
    }
    *(float4*)&red[a * 128 + 4 * c4] = make_float4(cs[0], cs[1], cs[2], cs[3]);
    __syncthreads();
    if (tid < 128) {
        float s = 0.f;
#pragma unroll
        for (int q = 0; q < 8; q++) s += red[q * 128 + tid];
        g_dpart[(b * 8 + jT) * NN + kT * 128 + tid] = s;
    }
    __syncthreads();

    // mirrored tile (kT rows, jT cols)
    if (jT != kT) {
        float cs2[4] = {0.f, 0.f, 0.f, 0.f};
#pragma unroll
        for (int it = 0; it < 16; it++) {
            int rr = a + 8 * it;
            int kg = kT * 128 + rr, jg = jT * 128 + 4 * c4;
            float4 av = *(const float4*)&adjb[(size_t)kg * NN + jg];
            float e0 = Ts[(4*c4+0) * TSTR + rr];
            float e1 = Ts[(4*c4+1) * TSTR + rr];
            float e2 = Ts[(4*c4+2) * TSTR + rr];
            float e3 = Ts[(4*c4+3) * TSTR + rr];
            float pv[4];
            pv[0] = (av.x > 0.f) ? __expf(e0) : 0.f;
            pv[1] = (av.y > 0.f) ? __expf(e1) : 0.f;
            pv[2] = (av.z > 0.f) ? __expf(e2) : 0.f;
            pv[3] = (av.w > 0.f) ? __expf(e3) : 0.f;
            cs2[0] += (av.x > 0.f) ? pv[0] : 1.f;
            cs2[1] += (av.y > 0.f) ? pv[1] : 1.f;
            cs2[2] += (av.z > 0.f) ? pv[2] : 1.f;
            cs2[3] += (av.w > 0.f) ? pv[3] : 1.f;
            __nv_bfloat16 h4[4], l4[4];
#pragma unroll
            for (int q = 0; q < 4; q++) split2(pv[q], h4[q], l4[q]);
            size_t o = (size_t)b * NN * NN + (size_t)kg * NN + jg;
            *(uint2*)&g_P1[o] = *(uint2*)h4;
            *(uint2*)&g_P2[o] = *(uint2*)l4;
        }
        __syncthreads();
        *(float4*)&red[a * 128 + 4 * c4] = make_float4(cs2[0], cs2[1], cs2[2], cs2[3]);
        __syncthreads();
        if (tid < 128) {
            float s = 0.f;
#pragma unroll
            for (int q = 0; q < 8; q++) s += red[q * 128 + tid];
            g_dpart[(b * 8 + kT) * NN + jT * 128 + tid] = s;
        }
    }
}

// ---------------------------------------------------------------------------
// K4: hscale — rden = 1/colsum from partials; hS = split(rden[j] * h[j][d])
// grid (16 jchunks, 16 b), 256 thr
// ---------------------------------------------------------------------------
__global__ void hscale_kernel() {
    __shared__ float rden[64];
    const int tid = threadIdx.x;
    const int b = blockIdx.y;
    const int j0 = blockIdx.x * 64;
    if (tid < 64) {
        float s = 0.f;
#pragma unroll
        for (int seg = 0; seg < 8; seg++)
            s += g_dpart[(b * 8 + seg) * NN + j0 + tid];
        rden[tid] = 1.0f / s;
    }
    __syncthreads();
#pragma unroll
    for (int it = 0; it < 4; it++) {
        int u = tid + it * 256;              // 1024 units: 128 d x 8 groups
        int d = u >> 3, g = u & 7;
        size_t o = ((size_t)(b * DD + d)) * NN + j0 + g * 8;
        uint4 v1 = *(const uint4*)&g_hT1[o];
        uint4 v2 = *(const uint4*)&g_hT2[o];
        const __nv_bfloat16* p1 = (const __nv_bfloat16*)&v1;
        const __nv_bfloat16* p2 = (const __nv_bfloat16*)&v2;
        __nv_bfloat16 s1[8], s2[8];
#pragma unroll
        for (int q = 0; q < 8; q++) {
            float hv = __bfloat162float(p1[q]) + __bfloat162float(p2[q]);
            split2(hv * rden[g * 8 + q], s1[q], s2[q]);
        }
        *(uint4*)&g_hS1[o] = *(uint4*)s1;
        *(uint4*)&g_hS2[o] = *(uint4*)s2;
    }
}

// ---------------------------------------------------------------------------
// K5: aggregation — pure cp.async mainloop + fused gates.
// h'[i,d] = sum_j P[i,j]*hS[d,j]; grid (16 iT, 16 b), 2 CTA/SM.
// ---------------------------------------------------------------------------
#define AG_A1 0
#define AG_A2 MATB64
#define AG_B1 (2*MATB64)
#define AG_B2 (2*MATB64 + MATB)
#define AG_SMEM (2*MATB64 + 2*MATB)   // 55296

__global__ void __launch_bounds__(256, 2)
agg_mma_kernel(const float* __restrict__ x,
               const float* __restrict__ wiu, const float* __restrict__ wix,
               const float* __restrict__ wfu, const float* __restrict__ wfx,
               const float* __restrict__ wou, const float* __restrict__ wox,
               float* __restrict__ out) {
    extern __shared__ char smem[];
    const uint32_t sb = smem_u32(smem);
    const int tid = threadIdx.x;
    const int wid = tid >> 5, lane = tid & 31;
    const int b = blockIdx.y;
    const int i0 = blockIdx.x * 64;
    const int mrow = (wid >> 2) * 32, ncol = (wid & 3) * 32;
    const int lg = lane >> 3, lr = lane & 7;

    float acc[32];
#pragma unroll
    for (int i = 0; i < 32; i++) acc[i] = 0.f;

    for (int c = 0; c < 16; c++) {
        const int j0 = c * 64;
        if (c) __syncthreads();
        // A: P1/P2 tiles [64 i x 64 j]
#pragma unroll
        for (int it = 0; it < 2; it++) {
            int row = it * 32 + (tid >> 3), f8 = tid & 7;
            size_t so = ((size_t)(b * NN + i0 + row)) * NN + j0 + f8 * 8;
            uint32_t off = row * (LDO*2) + f8 * 16;
            CP_ASYNC16(sb + AG_A1 + off, (const void*)&g_P1[so]);
            CP_ASYNC16(sb + AG_A2 + off, (const void*)&g_P2[so]);
        }
        // B: hS1/hS2 tiles [128 d x 64 j]
#pragma unroll
        for (int it = 0; it < 4; it++) {
            int row = it * 32 + (tid >> 3), f8 = tid & 7;
            size_t so = ((size_t)(b * DD + row)) * NN + j0 + f8 * 8;
            uint32_t off = row * (LDO*2) + f8 * 16;
            CP_ASYNC16(sb + AG_B1 + off, (const void*)&g_hS1[so]);
            CP_ASYNC16(sb + AG_B2 + off, (const void*)&g_hS2[so]);
        }
        CP_COMMIT();
        CP_WAIT0();
        __syncthreads();
        // mma: fragment reuse, M=64 (mi<2), N=32 per warp
#pragma unroll
        for (int ks = 0; ks < 4; ks++) {
            const int kk = ks * 16;
            uint32_t a1f[2][4], a2f[2][4];
#pragma unroll
            for (int mi = 0; mi < 2; mi++) {
                uint32_t ro = ((mrow + mi*16 + (lane & 15)) * LDO + kk + (lane >> 4) * 8) * 2;
                ldsm4(a1f[mi], sb + AG_A1 + ro);
                ldsm4(a2f[mi], sb + AG_A2 + ro);
            }
            uint32_t bf[2][4];
#pragma unroll
            for (int nb = 0; nb < 2; nb++) {
                int n = ncol + nb * 16 + (lg >> 1) * 8 + lr;
                ldsm4(bf[nb], sb + AG_B1 + (n * LDO + kk + (lg & 1) * 8) * 2);
            }
#pragma unroll
            for (int mi = 0; mi < 2; mi++)
#pragma unroll
                for (int ni = 0; ni < 4; ni++) {
                    mma16816(&acc[(mi*4+ni)*4], a1f[mi], &bf[ni>>1][(ni&1)*2]);
                    mma16816(&acc[(mi*4+ni)*4], a2f[mi], &bf[ni>>1][(ni&1)*2]);
                }
#pragma unroll
            for (int nb = 0; nb < 2; nb++) {
                int n = ncol + nb * 16 + (lg >> 1) * 8 + lr;
                ldsm4(bf[nb], sb + AG_B2 + (n * LDO + kk + (lg & 1) * 8) * 2);
            }
#pragma unroll
            for (int mi = 0; mi < 2; mi++)
#pragma unroll
                for (int ni = 0; ni < 4; ni++)
                    mma16816(&acc[(mi*4+ni)*4], a1f[mi], &bf[ni>>1][(ni&1)*2]);
        }
    }

    // h' = relu(acc) -> hp [64][132]
    __syncthreads();
    float* hp = (float*)smem;
#pragma unroll
    for (int mi = 0; mi < 2; mi++)
#pragma unroll
        for (int ni = 0; ni < 4; ni++) {
            int row = mrow + mi*16 + (lane >> 2);
            int col = ncol + ni*8 + (lane & 3) * 2;
            float* cc = &acc[(mi*4+ni)*4];
            hp[row * 132 + col]         = fmaxf(cc[0], 0.f);
            hp[row * 132 + col + 1]     = fmaxf(cc[1], 0.f);
            hp[(row+8) * 132 + col]     = fmaxf(cc[2], 0.f);
            hp[(row+8) * 132 + col + 1] = fmaxf(cc[3], 0.f);
        }
    __syncthreads();

    float4 ui = *(const float4*)&wiu[lane * 4];
    float4 xi = *(const float4*)&wix[lane * 4];
    float4 uf = *(const float4*)&wfu[lane * 4];
    float4 xf = *(const float4*)&wfx[lane * 4];
    float4 uo = *(const float4*)&wou[lane * 4];
    float4 xo = *(const float4*)&wox[lane * 4];

    for (int r = wid; r < 64; r += 8) {
        size_t n = (size_t)b * NN + i0 + r;
        float4 h4 = *(const float4*)&hp[r * 132 + lane * 4];
        float4 x4 = *(const float4*)&x[n * DD + lane * 4];
        float zi = h4.x*ui.x + h4.y*ui.y + h4.z*ui.z + h4.w*ui.w
                 + x4.x*xi.x + x4.y*xi.y + x4.z*xi.z + x4.w*xi.w;
        float zf = h4.x*uf.x + h4.y*uf.y + h4.z*uf.z + h4.w*uf.w
                 + x4.x*xf.x + x4.y*xf.y + x4.z*xf.z + x4.w*xf.w;
        float zo = h4.x*uo.x + h4.y*uo.y + h4.z*uo.z + h4.w*uo.w
                 + x4.x*xo.x + x4.y*xo.y + x4.z*xo.z + x4.w*xo.w;
#pragma unroll
        for (int off = 16; off; off >>= 1) {
            zi += __shfl_xor_sync(0xffffffffu, zi, off);
            zf += __shfl_xor_sync(0xffffffffu, zf, off);
            zo += __shfl_xor_sync(0xffffffffu, zo, off);
        }
        float ic = 1.f / (1.f + expf(-zi));
        float fc = 1.f / (1.f + expf(-zf));
        float oc = 1.f / (1.f + expf(-zo));
        float4 o;
        o.x = oc * tanhf(ic * h4.x + fc * x4.x);
        o.y = oc * tanhf(ic * h4.y + fc * x4.y);
        o.z = oc * tanhf(ic * h4.z + fc * x4.z);
        o.w = oc * tanhf(ic * h4.w + fc * x4.w);
        *(float4*)&out[n * DD + lane * 4] = o;
    }
}

// ---------------------------------------------------------------------------
extern "C" void kernel_launch(void* const* d_in, const int* in_sizes, int n_in,
                              void* d_out, int out_size) {
    const float* x   = (const float*)d_in[0];
    const float* adj = (const float*)d_in[1];
    const float* Ww  = (const float*)d_in[2];
    const float* Wb  = (const float*)d_in[3];
    const float* A   = (const float*)d_in[4];
    const float* wiu = (const float*)d_in[5];
    const float* wix = (const float*)d_in[6];
    const float* wfu = (const float*)d_in[7];
    const float* wfx = (const float*)d_in[8];
    const float* wou = (const float*)d_in[9];
    const float* wox = (const float*)d_in[10];
    float* out = (float*)d_out;

    cudaFuncSetAttribute((const void*)gemmht_kernel,
                         cudaFuncAttributeMaxDynamicSharedMemorySize, 131072);
    cudaFuncSetAttribute((const void*)scores_mma_kernel,
                         cudaFuncAttributeMaxDynamicSharedMemorySize, SC_SMEM);
    cudaFuncSetAttribute((const void*)agg_mma_kernel,
                         cudaFuncAttributeMaxDynamicSharedMemorySize, AG_SMEM);

    prep_M2_kernel<<<16, 256>>>(Ww, Wb, A);
    gemmht_kernel<<<dim3(128, 2), 256, 131072>>>(x, Ww, Wb);
    scores_mma_kernel<<<dim3(36, 16), 256, SC_SMEM>>>(adj);
    hscale_kernel<<<dim3(16, 16), 256>>>();
    agg_mma_kernel<<<dim3(16, 16), 256, AG_SMEM>>>(x, wiu, wix, wfu, wfx, wou, wox, out);
}

// round 13
// speedup vs baseline: 1.1054x; 1.1054x over previous
#include <cuda_runtime.h>
#include <cuda_fp16.h>
#include <cstdint>

#define BB 16
#define NN 1024
#define DD 128
#define BN (BB*NN)

// ---------------- scratch (device globals) ----------------
__device__ float  g_M2[DD*DD];                   // Ww^T @ A
__device__ float  g_b2[DD];                      // Wb @ A
__device__ __half g_u1[(size_t)BN*256];          // [t|h] fp16 hi   (v = halves swapped)
__device__ __half g_u2[(size_t)BN*256];          // [t|h] fp16 lo
__device__ float  g_hTf[(size_t)BB*DD*NN];       // hT[b][d][j] fp32
__device__ __half g_hS1[(size_t)BB*DD*NN];       // fp16(rden[j]*h[j][d])
__device__ __half g_P1[(size_t)BB*NN*NN];        // 32 MB exp(e-10) hi (0 if masked)
__device__ __half g_P2[(size_t)BB*NN*NN];        // 32 MB lo
__device__ float  g_dpart[BB*8*NN];              // column-sum partials per row-tile

#define SHIFTC  10.0f
#define EXPM10  4.5399930e-05f   // exp(-10): masked contribution to shifted colsum

// ---------------- helpers ----------------
__device__ __forceinline__ uint32_t smem_u32(const void* p) {
    uint32_t a;
    asm("{ .reg .u64 t; cvta.to.shared.u64 t, %1; cvt.u32.u64 %0, t; }" : "=r"(a) : "l"(p));
    return a;
}
__device__ __forceinline__ void ldsm4(uint32_t* r, uint32_t addr) {
    asm volatile("ldmatrix.sync.aligned.m8n8.x4.shared.b16 {%0,%1,%2,%3}, [%4];"
                 : "=r"(r[0]), "=r"(r[1]), "=r"(r[2]), "=r"(r[3]) : "r"(addr));
}
__device__ __forceinline__ void mma16816h(float* c, const uint32_t* a, const uint32_t* b) {
    asm volatile("mma.sync.aligned.m16n8k16.row.col.f32.f16.f16.f32 "
                 "{%0,%1,%2,%3}, {%4,%5,%6,%7}, {%8,%9}, {%0,%1,%2,%3};"
                 : "+f"(c[0]), "+f"(c[1]), "+f"(c[2]), "+f"(c[3])
                 : "r"(a[0]), "r"(a[1]), "r"(a[2]), "r"(a[3]), "r"(b[0]), "r"(b[1]));
}
#define CP_ASYNC16(dst, src) \
    asm volatile("cp.async.cg.shared.global [%0], [%1], 16;" :: "r"(dst), "l"(src) : "memory")
#define CP_COMMIT() asm volatile("cp.async.commit_group;" ::: "memory")
#define CP_WAIT0()  asm volatile("cp.async.wait_group 0;" ::: "memory")

#define LDO 72            // fp16 elems per smem row (64 data + 8 pad)
#define MATB (128*LDO*2)  // 18432 bytes per staged 128x64 matrix
#define MATB64 (64*LDO*2) // 9216 bytes per staged 64x64 matrix
#define TSTR 129          // float stride for transpose staging (scalar access only)

__device__ __forceinline__ void split2h(float v, __half& hi, __half& lo) {
    hi = __float2half_rn(v);
    lo = __float2half_rn(v - __half2float(hi));
}

// ---------------------------------------------------------------------------
// prep: M2 = Ww^T @ A,  b2 = Wb @ A
// ---------------------------------------------------------------------------
__global__ void prep_M2_kernel(const float* __restrict__ Ww,
                               const float* __restrict__ Wb,
                               const float* __restrict__ A) {
    __shared__ float As[128 * 8];
    const int tid = threadIdx.x;
    const int l0 = blockIdx.x * 8;
#pragma unroll
    for (int q = 0; q < 4; q++) {
        int idx = tid + q * 256;
        int d = idx >> 3, l = idx & 7;
        As[d * 8 + l] = A[d * 128 + l0 + l];
    }
    __syncthreads();
    const int f = tid & 127, g = tid >> 7;
    float s[4] = {0.f, 0.f, 0.f, 0.f};
    for (int d = 0; d < 128; d++) {
        float w = Ww[d * 128 + f];
#pragma unroll
        for (int q = 0; q < 4; q++)
            s[q] += w * As[d * 8 + g * 4 + q];
    }
    *(float4*)&g_M2[f * 128 + l0 + g * 4] = make_float4(s[0], s[1], s[2], s[3]);
    if (tid < 8) {
        float sb2 = 0.f;
        for (int d = 0; d < 128; d++)
            sb2 += Wb[d] * As[d * 8 + tid];
        g_b2[l0 + tid] = sb2;
    }
}

// ---------------------------------------------------------------------------
// fused GEMM: path 0: h = x@Ww^T + Wb -> u[:,128:256] fp16 pair, hTf fp32
//             path 1: t = x@M2   + b2 -> u[:,0:128]   fp16 pair
// ---------------------------------------------------------------------------
template<int LDA, int LDB>
__device__ __forceinline__ void mm8x8x4(const float* As, const float* Bs,
                                        int r0, int c0, int l, float acc[8][8]) {
    float a[8][4], bb[4][8];
#pragma unroll
    for (int i = 0; i < 8; i++) {
        float4 v = *(const float4*)&As[(r0 + i) * LDA + l];
        a[i][0]=v.x; a[i][1]=v.y; a[i][2]=v.z; a[i][3]=v.w;
    }
#pragma unroll
    for (int q = 0; q < 4; q++) {
        float4 v0 = *(const float4*)&Bs[(l + q) * LDB + c0];
        float4 v1 = *(const float4*)&Bs[(l + q) * LDB + c0 + 4];
        bb[q][0]=v0.x; bb[q][1]=v0.y; bb[q][2]=v0.z; bb[q][3]=v0.w;
        bb[q][4]=v1.x; bb[q][5]=v1.y; bb[q][6]=v1.z; bb[q][7]=v1.w;
    }
#pragma unroll
    for (int q = 0; q < 4; q++)
#pragma unroll
        for (int i = 0; i < 8; i++)
#pragma unroll
            for (int j = 0; j < 8; j++)
                acc[i][j] += a[i][q] * bb[q][j];
}

__global__ void __launch_bounds__(256, 1)
gemmht_kernel(const float* __restrict__ x, const float* __restrict__ Ww,
              const float* __restrict__ Wb) {
    extern __shared__ float smemf[];
    float* As = smemf;
    float* Bs = smemf + 128 * 128;
    const int tid = threadIdx.x;
    const int m0 = blockIdx.x * 128;
    const int path = blockIdx.y;

    const float4* Ag = (const float4*)(x + (size_t)m0 * 128);
#pragma unroll
    for (int it = 0; it < 16; it++)
        ((float4*)As)[tid + it * 256] = Ag[tid + it * 256];
    if (path == 0) {
#pragma unroll
        for (int it = 0; it < 16; it++) {
            int lin = tid + it * 256;
            int c = lin & 127, k4 = lin >> 7;
            float4 v = ((const float4*)Ww)[c * 32 + k4];
            Bs[(4*k4+0)*128+c]=v.x; Bs[(4*k4+1)*128+c]=v.y;
            Bs[(4*k4+2)*128+c]=v.z; Bs[(4*k4+3)*128+c]=v.w;
        }
    } else {
#pragma unroll
        for (int it = 0; it < 16; it++)
            ((float4*)Bs)[tid + it * 256] = ((const float4*)g_M2)[tid + it * 256];
    }
    __syncthreads();
    const int r0 = (tid >> 4) * 8, c0 = (tid & 15) * 8;
    float acc[8][8] = {};
#pragma unroll
    for (int l = 0; l < 128; l += 4)
        mm8x8x4<128, 128>(As, Bs, r0, c0, l, acc);

    const float* bias = path ? g_b2 : Wb;
    float bv[8];
#pragma unroll
    for (int j = 0; j < 8; j++) bv[j] = bias[c0 + j];
#pragma unroll
    for (int i = 0; i < 8; i++)
#pragma unroll
        for (int j = 0; j < 8; j++)
            acc[i][j] += bv[j];

    // write u fp16 splits (u=[t|h]); v is u with halves swapped (no storage)
#pragma unroll
    for (int i = 0; i < 8; i++) {
        int node = m0 + r0 + i;
        __half hi[8], lo[8];
#pragma unroll
        for (int j = 0; j < 8; j++) split2h(acc[i][j], hi[j], lo[j]);
        size_t bu = (size_t)node * 256 + c0 + (path ? 0 : 128);
        *(uint4*)&g_u1[bu] = *(uint4*)hi;
        *(uint4*)&g_u2[bu] = *(uint4*)lo;
    }

    if (path == 0) {
        // hTf[b][d][j] fp32 via smem transpose (scalar smem access, stride 129)
        __syncthreads();
        float* Ts = smemf;   // [128][TSTR]
#pragma unroll
        for (int i = 0; i < 8; i++)
#pragma unroll
            for (int j = 0; j < 8; j++)
                Ts[(r0 + i) * TSTR + c0 + j] = acc[i][j];
        __syncthreads();
        const int bb_ = m0 >> 10, j0 = m0 & 1023;
#pragma unroll
        for (int it = 0; it < 32; it++) {
            int idx = it * 256 + tid;
            int d = idx >> 6, jp = idx & 63;
            float v0 = Ts[(2 * jp) * TSTR + d];
            float v1 = Ts[(2 * jp + 1) * TSTR + d];
            size_t o = ((size_t)bb_ * DD + d) * NN + j0 + 2 * jp;
            *(float2*)&g_hTf[o] = make_float2(v0, v1);
        }
    }
}

// ---------------------------------------------------------------------------
// K3: scores. grid (36 pairs, 16 b), 256 thr, 2 CTA/SM.
// e[j,k] = (u1_j+u2_j)·v1_k (2 fp16 products); P = adj>0 ? exp(e-10) : 0
// v1 = u1 with k-halves swapped. Fused column-sum partials (masked -> exp(-10)).
// ---------------------------------------------------------------------------
#define SC_SMEM 70144   // mats 3*18432=55296; epilogue Ts[128][129] (66048) + red (4096)

__global__ void __launch_bounds__(256, 2)
scores_mma_kernel(const float* __restrict__ adj) {
    extern __shared__ char smem[];
    const uint32_t sb = smem_u32(smem);
    float* Ts = (float*)smem;
    float* red = (float*)(smem + 66048);

    const int tid = threadIdx.x;
    const int wid = tid >> 5, lane = tid & 31;
    const int b = blockIdx.y;
    int p = blockIdx.x, jT = 0;
    while (p >= 8 - jT) { p -= 8 - jT; jT++; }
    const int kT = jT + p;

    const int mrow = (wid >> 1) * 32, ncol = (wid & 1) * 64;
    const int lg = lane >> 3, lr = lane & 7;
    float acc[64];
#pragma unroll
    for (int i = 0; i < 64; i++) acc[i] = 0.f;

#pragma unroll
    for (int chunk = 0; chunk < 4; chunk++) {
        const int k0 = chunk * 64;
        const int k0sw = (k0 + 128) & 255;
        if (chunk) __syncthreads();
        // stage: mat0 = u1@jT (A1), mat1 = u2@jT (A2), mat2 = u1@kT swapped-k (B)
#pragma unroll
        for (int it = 0; it < 4; it++) {
            int row = it * 32 + (tid >> 3), f8 = tid & 7;
            uint32_t off = row * (LDO*2) + f8 * 16;
            CP_ASYNC16(sb + off,
                       (const void*)&g_u1[((size_t)(b * NN + jT * 128 + row)) * 256 + k0 + f8 * 8]);
            CP_ASYNC16(sb + MATB + off,
                       (const void*)&g_u2[((size_t)(b * NN + jT * 128 + row)) * 256 + k0 + f8 * 8]);
            CP_ASYNC16(sb + 2 * MATB + off,
                       (const void*)&g_u1[((size_t)(b * NN + kT * 128 + row)) * 256 + k0sw + f8 * 8]);
        }
        CP_COMMIT();
        CP_WAIT0();
        __syncthreads();
        // mma: per k-slice load a1,a2,b once; 2 products
#pragma unroll
        for (int ks = 0; ks < 4; ks++) {
            const int kk = ks * 16;
            uint32_t a1f[2][4], a2f[2][4];
#pragma unroll
            for (int mi = 0; mi < 2; mi++) {
                uint32_t ro = ((mrow + mi*16 + (lane & 15)) * LDO + kk + (lane >> 4) * 8) * 2;
                ldsm4(a1f[mi], sb + ro);
                ldsm4(a2f[mi], sb + MATB + ro);
            }
            uint32_t bf[4][4];
#pragma unroll
            for (int nb = 0; nb < 4; nb++) {
                int n = ncol + nb * 16 + (lg >> 1) * 8 + lr;
                ldsm4(bf[nb], sb + 2 * MATB + (n * LDO + kk + (lg & 1) * 8) * 2);
            }
#pragma unroll
            for (int mi = 0; mi < 2; mi++)
#pragma unroll
                for (int ni = 0; ni < 8; ni++) {
                    mma16816h(&acc[(mi*8+ni)*4], a1f[mi], &bf[ni>>1][(ni&1)*2]);
                    mma16816h(&acc[(mi*8+ni)*4], a2f[mi], &bf[ni>>1][(ni&1)*2]);
                }
        }
    }

    __syncthreads();
#pragma unroll
    for (int mi = 0; mi < 2; mi++)
#pragma unroll
        for (int ni = 0; ni < 8; ni++) {
            int row = mrow + mi*16 + (lane >> 2);
            int col = ncol + ni*8 + (lane & 3) * 2;
            float* c = &acc[(mi*8+ni)*4];
            Ts[row * TSTR + col]           = c[0];
            Ts[row * TSTR + col + 1]       = c[1];
            Ts[(row + 8) * TSTR + col]     = c[2];
            Ts[(row + 8) * TSTR + col + 1] = c[3];
        }
    __syncthreads();

    const float* adjb = adj + (size_t)b * NN * NN;
    const int a = tid >> 5, c4 = tid & 31;

    // direct tile (jT rows, kT cols): shifted-exp fp16 P splits + colsum partials
    float cs[4] = {0.f, 0.f, 0.f, 0.f};
#pragma unroll
    for (int it = 0; it < 16; it++) {
        int rr = a + 8 * it;
        int jg = jT * 128 + rr, kg = kT * 128 + 4 * c4;
        float4 av = *(const float4*)&adjb[(size_t)jg * NN + kg];
        const float* tr = &Ts[rr * TSTR + 4 * c4];
        float pv[4];
        pv[0] = (av.x > 0.f) ? __expf(tr[0] - SHIFTC) : 0.f;
        pv[1] = (av.y > 0.f) ? __expf(tr[1] - SHIFTC) : 0.f;
        pv[2] = (av.z > 0.f) ? __expf(tr[2] - SHIFTC) : 0.f;
        pv[3] = (av.w > 0.f) ? __expf(tr[3] - SHIFTC) : 0.f;
        cs[0] += (av.x > 0.f) ? pv[0] : EXPM10;
        cs[1] += (av.y > 0.f) ? pv[1] : EXPM10;
        cs[2] += (av.z > 0.f) ? pv[2] : EXPM10;
        cs[3] += (av.w > 0.f) ? pv[3] : EXPM10;
        __half h4[4], l4[4];
#pragma unroll
        for (int q = 0; q < 4; q++) split2h(pv[q], h4[q], l4[q]);
        size_t o = (size_t)b * NN * NN + (size_t)jg * NN + kg;
        *(uint2*)&g_P1[o] = *(uint2*)h4;
        *(uint2*)&g_P2[o] = *(uint2*)l4;
    }
    *(float4*)&red[a * 128 + 4 * c4] = make_float4(cs[0], cs[1], cs[2], cs[3]);
    __syncthreads();
    if (tid < 128) {
        float s = 0.f;
#pragma unroll
        for (int q = 0; q < 8; q++) s += red[q * 128 + tid];
        g_dpart[(b * 8 + jT) * NN + kT * 128 + tid] = s;
    }
    __syncthreads();

    // mirrored tile (kT rows, jT cols)
    if (jT != kT) {
        float cs2[4] = {0.f, 0.f, 0.f, 0.f};
#pragma unroll
        for (int it = 0; it < 16; it++) {
            int rr = a + 8 * it;
            int kg = kT * 128 + rr, jg = jT * 128 + 4 * c4;
            float4 av = *(const float4*)&adjb[(size_t)kg * NN + jg];
            float e0 = Ts[(4*c4+0) * TSTR + rr];
            float e1 = Ts[(4*c4+1) * TSTR + rr];
            float e2 = Ts[(4*c4+2) * TSTR + rr];
            float e3 = Ts[(4*c4+3) * TSTR + rr];
            float pv[4];
            pv[0] = (av.x > 0.f) ? __expf(e0 - SHIFTC) : 0.f;
            pv[1] = (av.y > 0.f) ? __expf(e1 - SHIFTC) : 0.f;
            pv[2] = (av.z > 0.f) ? __expf(e2 - SHIFTC) : 0.f;
            pv[3] = (av.w > 0.f) ? __expf(e3 - SHIFTC) : 0.f;
            cs2[0] += (av.x > 0.f) ? pv[0] : EXPM10;
            cs2[1] += (av.y > 0.f) ? pv[1] : EXPM10;
            cs2[2] += (av.z > 0.f) ? pv[2] : EXPM10;
            cs2[3] += (av.w > 0.f) ? pv[3] : EXPM10;
            __half h4[4], l4[4];
#pragma unroll
            for (int q = 0; q < 4; q++) split2h(pv[q], h4[q], l4[q]);
            size_t o = (size_t)b * NN * NN + (size_t)kg * NN + jg;
            *(uint2*)&g_P1[o] = *(uint2*)h4;
            *(uint2*)&g_P2[o] = *(uint2*)l4;
        }
        __syncthreads();
        *(float4*)&red[a * 128 + 4 * c4] = make_float4(cs2[0], cs2[1], cs2[2], cs2[3]);
        __syncthreads();
        if (tid < 128) {
            float s = 0.f;
#pragma unroll
            for (int q = 0; q < 8; q++) s += red[q * 128 + tid];
            g_dpart[(b * 8 + kT) * NN + jT * 128 + tid] = s;
        }
    }
}

// ---------------------------------------------------------------------------
// K4: hscale — rden = 1/colsum; hS1 = fp16(rden[j] * h[j][d])
// grid (16 jchunks, 16 b), 256 thr
// ---------------------------------------------------------------------------
__global__ void hscale_kernel() {
    __shared__ float rden[64];
    const int tid = threadIdx.x;
    const int b = blockIdx.y;
    const int j0 = blockIdx.x * 64;
    if (tid < 64) {
        float s = 0.f;
#pragma unroll
        for (int seg = 0; seg < 8; seg++)
            s += g_dpart[(b * 8 + seg) * NN + j0 + tid];
        rden[tid] = 1.0f / s;
    }
    __syncthreads();
#pragma unroll
    for (int it = 0; it < 4; it++) {
        int u = tid + it * 256;              // 1024 units: 128 d x 8 groups of 8 j
        int d = u >> 3, g = u & 7;
        size_t o = ((size_t)(b * DD + d)) * NN + j0 + g * 8;
        float4 va = *(const float4*)&g_hTf[o];
        float4 vb = *(const float4*)&g_hTf[o + 4];
        __half s1[8];
        s1[0] = __float2half_rn(va.x * rden[g*8+0]);
        s1[1] = __float2half_rn(va.y * rden[g*8+1]);
        s1[2] = __float2half_rn(va.z * rden[g*8+2]);
        s1[3] = __float2half_rn(va.w * rden[g*8+3]);
        s1[4] = __float2half_rn(vb.x * rden[g*8+4]);
        s1[5] = __float2half_rn(vb.y * rden[g*8+5]);
        s1[6] = __float2half_rn(vb.z * rden[g*8+6]);
        s1[7] = __float2half_rn(vb.w * rden[g*8+7]);
        *(uint4*)&g_hS1[o] = *(uint4*)s1;
    }
}

// ---------------------------------------------------------------------------
// K5: aggregation — h'[i,d] = sum_j (P1+P2)[i,j]*hS1[d,j]; 2 fp16 products.
// grid (16 iT, 16 b), 2 CTA/SM. Fused gate epilogue.
// ---------------------------------------------------------------------------
#define AG_A1 0
#define AG_A2 MATB64
#define AG_B  (2*MATB64)
#define AG_SMEM (2*MATB64 + MATB)   // 36864; epilogue hp 64*132*4 = 33792 fits

__global__ void __launch_bounds__(256, 2)
agg_mma_kernel(const float* __restrict__ x,
               const float* __restrict__ wiu, const float* __restrict__ wix,
               const float* __restrict__ wfu, const float* __restrict__ wfx,
               const float* __restrict__ wou, const float* __restrict__ wox,
               float* __restrict__ out) {
    extern __shared__ char smem[];
    const uint32_t sb = smem_u32(smem);
    const int tid = threadIdx.x;
    const int wid = tid >> 5, lane = tid & 31;
    const int b = blockIdx.y;
    const int i0 = blockIdx.x * 64;
    const int mrow = (wid >> 2) * 32, ncol = (wid & 3) * 32;
    const int lg = lane >> 3, lr = lane & 7;

    float acc[32];
#pragma unroll
    for (int i = 0; i < 32; i++) acc[i] = 0.f;

    for (int c = 0; c < 16; c++) {
        const int j0 = c * 64;
        if (c) __syncthreads();
        // A: P1/P2 tiles [64 i x 64 j]
#pragma unroll
        for (int it = 0; it < 2; it++) {
            int row = it * 32 + (tid >> 3), f8 = tid & 7;
            size_t so = ((size_t)(b * NN + i0 + row)) * NN + j0 + f8 * 8;
            uint32_t off = row * (LDO*2) + f8 * 16;
            CP_ASYNC16(sb + AG_A1 + off, (const void*)&g_P1[so]);
            CP_ASYNC16(sb + AG_A2 + off, (const void*)&g_P2[so]);
        }
        // B: hS1 tile [128 d x 64 j]
#pragma unroll
        for (int it = 0; it < 4; it++) {
            int row = it * 32 + (tid >> 3), f8 = tid & 7;
            size_t so = ((size_t)(b * DD + row)) * NN + j0 + f8 * 8;
            CP_ASYNC16(sb + AG_B + row * (LDO*2) + f8 * 16, (const void*)&g_hS1[so]);
        }
        CP_COMMIT();
        CP_WAIT0();
        __syncthreads();
        // mma: M=64 (mi<2), N=32 per warp, 2 products sharing B fragments
#pragma unroll
        for (int ks = 0; ks < 4; ks++) {
            const int kk = ks * 16;
            uint32_t a1f[2][4], a2f[2][4];
#pragma unroll
            for (int mi = 0; mi < 2; mi++) {
                uint32_t ro = ((mrow + mi*16 + (lane & 15)) * LDO + kk + (lane >> 4) * 8) * 2;
                ldsm4(a1f[mi], sb + AG_A1 + ro);
                ldsm4(a2f[mi], sb + AG_A2 + ro);
            }
            uint32_t bf[2][4];
#pragma unroll
            for (int nb = 0; nb < 2; nb++) {
                int n = ncol + nb * 16 + (lg >> 1) * 8 + lr;
                ldsm4(bf[nb], sb + AG_B + (n * LDO + kk + (lg & 1) * 8) * 2);
            }
#pragma unroll
            for (int mi = 0; mi < 2; mi++)
#pragma unroll
                for (int ni = 0; ni < 4; ni++) {
                    mma16816h(&acc[(mi*4+ni)*4], a1f[mi], &bf[ni>>1][(ni&1)*2]);
                    mma16816h(&acc[(mi*4+ni)*4], a2f[mi], &bf[ni>>1][(ni&1)*2]);
                }
        }
    }

    // h' = relu(acc) -> hp [64][132]
    __syncthreads();
    float* hp = (float*)smem;
#pragma unroll
    for (int mi = 0; mi < 2; mi++)
#pragma unroll
        for (int ni = 0; ni < 4; ni++) {
            int row = mrow + mi*16 + (lane >> 2);
            int col = ncol + ni*8 + (lane & 3) * 2;
            float* cc = &acc[(mi*4+ni)*4];
            hp[row * 132 + col]         = fmaxf(cc[0], 0.f);
            hp[row * 132 + col + 1]     = fmaxf(cc[1], 0.f);
            hp[(row+8) * 132 + col]     = fmaxf(cc[2], 0.f);
            hp[(row+8) * 132 + col + 1] = fmaxf(cc[3], 0.f);
        }
    __syncthreads();

    float4 ui = *(const float4*)&wiu[lane * 4];
    float4 xi = *(const float4*)&wix[lane * 4];
    float4 uf = *(const float4*)&wfu[lane * 4];
    float4 xf = *(const float4*)&wfx[lane * 4];
    float4 uo = *(const float4*)&wou[lane * 4];
    float4 xo = *(const float4*)&wox[lane * 4];

    for (int r = wid; r < 64; r += 8) {
        size_t n = (size_t)b * NN + i0 + r;
        float4 h4 = *(const float4*)&hp[r * 132 + lane * 4];
        float4 x4 = *(const float4*)&x[n * DD + lane * 4];
        float zi = h4.x*ui.x + h4.y*ui.y + h4.z*ui.z + h4.w*ui.w
                 + x4.x*xi.x + x4.y*xi.y + x4.z*xi.z + x4.w*xi.w;
        float zf = h4.x*uf.x + h4.y*uf.y + h4.z*uf.z + h4.w*uf.w
                 + x4.x*xf.x + x4.y*xf.y + x4.z*xf.z + x4.w*xf.w;
        float zo = h4.x*uo.x + h4.y*uo.y + h4.z*uo.z + h4.w*uo.w
                 + x4.x*xo.x + x4.y*xo.y + x4.z*xo.z + x4.w*xo.w;
#pragma unroll
        for (int off = 16; off; off >>= 1) {
            zi += __shfl_xor_sync(0xffffffffu, zi, off);
            zf += __shfl_xor_sync(0xffffffffu, zf, off);
            zo += __shfl_xor_sync(0xffffffffu, zo, off);
        }
        float ic = 1.f / (1.f + expf(-zi));
        float fc = 1.f / (1.f + expf(-zf));
        float oc = 1.f / (1.f + expf(-zo));
        float4 o;
        o.x = oc * tanhf(ic * h4.x + fc * x4.x);
        o.y = oc * tanhf(ic * h4.y + fc * x4.y);
        o.z = oc * tanhf(ic * h4.z + fc * x4.z);
        o.w = oc * tanhf(ic * h4.w + fc * x4.w);
        *(float4*)&out[n * DD + lane * 4] = o;
    }
}

// ---------------------------------------------------------------------------
extern "C" void kernel_launch(void* const* d_in, const int* in_sizes, int n_in,
                              void* d_out, int out_size) {
    const float* x   = (const float*)d_in[0];
    const float* adj = (const float*)d_in[1];
    const float* Ww  = (const float*)d_in[2];
    const float* Wb  = (const float*)d_in[3];
    const float* A   = (const float*)d_in[4];
    const float* wiu = (const float*)d_in[5];
    const float* wix = (const float*)d_in[6];
    const float* wfu = (const float*)d_in[7];
    const float* wfx = (const float*)d_in[8];
    const float* wou = (const float*)d_in[9];
    const float* wox = (const float*)d_in[10];
    float* out = (float*)d_out;

    cudaFuncSetAttribute((const void*)gemmht_kernel,
                         cudaFuncAttributeMaxDynamicSharedMemorySize, 131072);
    cudaFuncSetAttribute((const void*)scores_mma_kernel,
                         cudaFuncAttributeMaxDynamicSharedMemorySize, SC_SMEM);
    cudaFuncSetAttribute((const void*)agg_mma_kernel,
                         cudaFuncAttributeMaxDynamicSharedMemorySize, AG_SMEM);

    prep_M2_kernel<<<16, 256>>>(Ww, Wb, A);
    gemmht_kernel<<<dim3(128, 2), 256, 131072>>>(x, Ww, Wb);
    scores_mma_kernel<<<dim3(36, 16), 256, SC_SMEM>>>(adj);
    hscale_kernel<<<dim3(16, 16), 256>>>();
    agg_mma_kernel<<<dim3(16, 16), 256, AG_SMEM>>>(x, wiu, wix, wfu, wfx, wou, wox, out);
}

// round 14
// speedup vs baseline: 1.2584x; 1.1384x over previous
#include <cuda_runtime.h>
#include <cuda_fp16.h>
#include <cstdint>

#define BB 16
#define NN 1024
#define DD 128
#define BN (BB*NN)

// ---------------- scratch (device globals) ----------------
__device__ float  g_M2[DD*DD];                   // Ww^T @ A
__device__ float  g_b2[DD];                      // Wb @ A
__device__ __half g_u1[(size_t)BN*256];          // [t|h] fp16 hi   (v = halves swapped)
__device__ __half g_u2[(size_t)BN*256];          // [t|h] fp16 lo
__device__ float  g_hTf[(size_t)BB*DD*NN];       // hT[b][d][j] fp32
__device__ __half g_hS1[(size_t)BB*DD*NN];       // fp16(rden[j]*h[j][d])
__device__ __half g_P1[(size_t)BB*NN*NN];        // 32 MB fp16 exp(e-10) (0 if masked)
__device__ float  g_dpart[BB*8*NN];              // column-sum partials per row-tile

#define SHIFTC  10.0f
#define EXPM10  4.5399930e-05f   // exp(-10): masked contribution to shifted colsum

// ---------------- helpers ----------------
__device__ __forceinline__ uint32_t smem_u32(const void* p) {
    uint32_t a;
    asm("{ .reg .u64 t; cvta.to.shared.u64 t, %1; cvt.u32.u64 %0, t; }" : "=r"(a) : "l"(p));
    return a;
}
__device__ __forceinline__ void ldsm4(uint32_t* r, uint32_t addr) {
    asm volatile("ldmatrix.sync.aligned.m8n8.x4.shared.b16 {%0,%1,%2,%3}, [%4];"
                 : "=r"(r[0]), "=r"(r[1]), "=r"(r[2]), "=r"(r[3]) : "r"(addr));
}
__device__ __forceinline__ void mma16816h(float* c, const uint32_t* a, const uint32_t* b) {
    asm volatile("mma.sync.aligned.m16n8k16.row.col.f32.f16.f16.f32 "
                 "{%0,%1,%2,%3}, {%4,%5,%6,%7}, {%8,%9}, {%0,%1,%2,%3};"
                 : "+f"(c[0]), "+f"(c[1]), "+f"(c[2]), "+f"(c[3])
                 : "r"(a[0]), "r"(a[1]), "r"(a[2]), "r"(a[3]), "r"(b[0]), "r"(b[1]));
}
#define CP_ASYNC16(dst, src) \
    asm volatile("cp.async.cg.shared.global [%0], [%1], 16;" :: "r"(dst), "l"(src) : "memory")
#define CP_COMMIT() asm volatile("cp.async.commit_group;" ::: "memory")
#define CP_WAIT0()  asm volatile("cp.async.wait_group 0;" ::: "memory")

#define LDO 72            // fp16 elems per smem row (64 data + 8 pad)
#define MATB (128*LDO*2)  // 18432 bytes per staged 128x64 matrix
#define MATB64 (64*LDO*2) // 9216 bytes per staged 64x64 matrix
#define TSTR 129          // float stride for transpose staging (scalar access only)

__device__ __forceinline__ void split2h(float v, __half& hi, __half& lo) {
    hi = __float2half_rn(v);
    lo = __float2half_rn(v - __half2float(hi));
}

// ---------------------------------------------------------------------------
// prep: M2 = Ww^T @ A,  b2 = Wb @ A
// ---------------------------------------------------------------------------
__global__ void prep_M2_kernel(const float* __restrict__ Ww,
                               const float* __restrict__ Wb,
                               const float* __restrict__ A) {
    __shared__ float As[128 * 8];
    const int tid = threadIdx.x;
    const int l0 = blockIdx.x * 8;
#pragma unroll
    for (int q = 0; q < 4; q++) {
        int idx = tid + q * 256;
        int d = idx >> 3, l = idx & 7;
        As[d * 8 + l] = A[d * 128 + l0 + l];
    }
    __syncthreads();
    const int f = tid & 127, g = tid >> 7;
    float s[4] = {0.f, 0.f, 0.f, 0.f};
    for (int d = 0; d < 128; d++) {
        float w = Ww[d * 128 + f];
#pragma unroll
        for (int q = 0; q < 4; q++)
            s[q] += w * As[d * 8 + g * 4 + q];
    }
    *(float4*)&g_M2[f * 128 + l0 + g * 4] = make_float4(s[0], s[1], s[2], s[3]);
    if (tid < 8) {
        float sb2 = 0.f;
        for (int d = 0; d < 128; d++)
            sb2 += Wb[d] * As[d * 8 + tid];
        g_b2[l0 + tid] = sb2;
    }
}

// ---------------------------------------------------------------------------
// fused GEMM: path 0: h = x@Ww^T + Wb -> u[:,128:256] fp16 pair, hTf fp32
//             path 1: t = x@M2   + b2 -> u[:,0:128]   fp16 pair
// ---------------------------------------------------------------------------
template<int LDA, int LDB>
__device__ __forceinline__ void mm8x8x4(const float* As, const float* Bs,
                                        int r0, int c0, int l, float acc[8][8]) {
    float a[8][4], bb[4][8];
#pragma unroll
    for (int i = 0; i < 8; i++) {
        float4 v = *(const float4*)&As[(r0 + i) * LDA + l];
        a[i][0]=v.x; a[i][1]=v.y; a[i][2]=v.z; a[i][3]=v.w;
    }
#pragma unroll
    for (int q = 0; q < 4; q++) {
        float4 v0 = *(const float4*)&Bs[(l + q) * LDB + c0];
        float4 v1 = *(const float4*)&Bs[(l + q) * LDB + c0 + 4];
        bb[q][0]=v0.x; bb[q][1]=v0.y; bb[q][2]=v0.z; bb[q][3]=v0.w;
        bb[q][4]=v1.x; bb[q][5]=v1.y; bb[q][6]=v1.z; bb[q][7]=v1.w;
    }
#pragma unroll
    for (int q = 0; q < 4; q++)
#pragma unroll
        for (int i = 0; i < 8; i++)
#pragma unroll
            for (int j = 0; j < 8; j++)
                acc[i][j] += a[i][q] * bb[q][j];
}

__global__ void __launch_bounds__(256, 1)
gemmht_kernel(const float* __restrict__ x, const float* __restrict__ Ww,
              const float* __restrict__ Wb) {
    extern __shared__ float smemf[];
    float* As = smemf;
    float* Bs = smemf + 128 * 128;
    const int tid = threadIdx.x;
    const int m0 = blockIdx.x * 128;
    const int path = blockIdx.y;

    const float4* Ag = (const float4*)(x + (size_t)m0 * 128);
#pragma unroll
    for (int it = 0; it < 16; it++)
        ((float4*)As)[tid + it * 256] = Ag[tid + it * 256];
    if (path == 0) {
#pragma unroll
        for (int it = 0; it < 16; it++) {
            int lin = tid + it * 256;
            int c = lin & 127, k4 = lin >> 7;
            float4 v = ((const float4*)Ww)[c * 32 + k4];
            Bs[(4*k4+0)*128+c]=v.x; Bs[(4*k4+1)*128+c]=v.y;
            Bs[(4*k4+2)*128+c]=v.z; Bs[(4*k4+3)*128+c]=v.w;
        }
    } else {
#pragma unroll
        for (int it = 0; it < 16; it++)
            ((float4*)Bs)[tid + it * 256] = ((const float4*)g_M2)[tid + it * 256];
    }
    __syncthreads();
    const int r0 = (tid >> 4) * 8, c0 = (tid & 15) * 8;
    float acc[8][8] = {};
#pragma unroll
    for (int l = 0; l < 128; l += 4)
        mm8x8x4<128, 128>(As, Bs, r0, c0, l, acc);

    const float* bias = path ? g_b2 : Wb;
    float bv[8];
#pragma unroll
    for (int j = 0; j < 8; j++) bv[j] = bias[c0 + j];
#pragma unroll
    for (int i = 0; i < 8; i++)
#pragma unroll
        for (int j = 0; j < 8; j++)
            acc[i][j] += bv[j];

    // write u fp16 splits (u=[t|h]); v is u with halves swapped (no storage)
#pragma unroll
    for (int i = 0; i < 8; i++) {
        int node = m0 + r0 + i;
        __half hi[8], lo[8];
#pragma unroll
        for (int j = 0; j < 8; j++) split2h(acc[i][j], hi[j], lo[j]);
        size_t bu = (size_t)node * 256 + c0 + (path ? 0 : 128);
        *(uint4*)&g_u1[bu] = *(uint4*)hi;
        *(uint4*)&g_u2[bu] = *(uint4*)lo;
    }

    if (path == 0) {
        // hTf[b][d][j] fp32 via smem transpose (scalar smem access, stride 129)
        __syncthreads();
        float* Ts = smemf;   // [128][TSTR]
#pragma unroll
        for (int i = 0; i < 8; i++)
#pragma unroll
            for (int j = 0; j < 8; j++)
                Ts[(r0 + i) * TSTR + c0 + j] = acc[i][j];
        __syncthreads();
        const int bb_ = m0 >> 10, j0 = m0 & 1023;
#pragma unroll
        for (int it = 0; it < 32; it++) {
            int idx = it * 256 + tid;
            int d = idx >> 6, jp = idx & 63;
            float v0 = Ts[(2 * jp) * TSTR + d];
            float v1 = Ts[(2 * jp + 1) * TSTR + d];
            size_t o = ((size_t)bb_ * DD + d) * NN + j0 + 2 * jp;
            *(float2*)&g_hTf[o] = make_float2(v0, v1);
        }
    }
}

// ---------------------------------------------------------------------------
// K3: scores. grid (36 pairs, 16 b), 256 thr, 2 CTA/SM.
// e[j,k] = (u1_j+u2_j)·v1_k (2 fp16 products); P = adj>0 ? fp16(exp(e-10)) : 0
// v1 = u1 with k-halves swapped. Fused column-sum partials (masked -> exp(-10)).
// ---------------------------------------------------------------------------
#define SC_SMEM 70144   // mats 3*18432=55296; epilogue Ts[128][129] (66048) + red (4096)

__global__ void __launch_bounds__(256, 2)
scores_mma_kernel(const float* __restrict__ adj) {
    extern __shared__ char smem[];
    const uint32_t sb = smem_u32(smem);
    float* Ts = (float*)smem;
    float* red = (float*)(smem + 66048);

    const int tid = threadIdx.x;
    const int wid = tid >> 5, lane = tid & 31;
    const int b = blockIdx.y;
    int p = blockIdx.x, jT = 0;
    while (p >= 8 - jT) { p -= 8 - jT; jT++; }
    const int kT = jT + p;

    const int mrow = (wid >> 1) * 32, ncol = (wid & 1) * 64;
    const int lg = lane >> 3, lr = lane & 7;
    float acc[64];
#pragma unroll
    for (int i = 0; i < 64; i++) acc[i] = 0.f;

#pragma unroll
    for (int chunk = 0; chunk < 4; chunk++) {
        const int k0 = chunk * 64;
        const int k0sw = (k0 + 128) & 255;
        if (chunk) __syncthreads();
        // stage: mat0 = u1@jT (A1), mat1 = u2@jT (A2), mat2 = u1@kT swapped-k (B)
#pragma unroll
        for (int it = 0; it < 4; it++) {
            int row = it * 32 + (tid >> 3), f8 = tid & 7;
            uint32_t off = row * (LDO*2) + f8 * 16;
            CP_ASYNC16(sb + off,
                       (const void*)&g_u1[((size_t)(b * NN + jT * 128 + row)) * 256 + k0 + f8 * 8]);
            CP_ASYNC16(sb + MATB + off,
                       (const void*)&g_u2[((size_t)(b * NN + jT * 128 + row)) * 256 + k0 + f8 * 8]);
            CP_ASYNC16(sb + 2 * MATB + off,
                       (const void*)&g_u1[((size_t)(b * NN + kT * 128 + row)) * 256 + k0sw + f8 * 8]);
        }
        CP_COMMIT();
        CP_WAIT0();
        __syncthreads();
        // mma: per k-slice load a1,a2,b once; 2 products
#pragma unroll
        for (int ks = 0; ks < 4; ks++) {
            const int kk = ks * 16;
            uint32_t a1f[2][4], a2f[2][4];
#pragma unroll
            for (int mi = 0; mi < 2; mi++) {
                uint32_t ro = ((mrow + mi*16 + (lane & 15)) * LDO + kk + (lane >> 4) * 8) * 2;
                ldsm4(a1f[mi], sb + ro);
                ldsm4(a2f[mi], sb + MATB + ro);
            }
            uint32_t bf[4][4];
#pragma unroll
            for (int nb = 0; nb < 4; nb++) {
                int n = ncol + nb * 16 + (lg >> 1) * 8 + lr;
                ldsm4(bf[nb], sb + 2 * MATB + (n * LDO + kk + (lg & 1) * 8) * 2);
            }
#pragma unroll
            for (int mi = 0; mi < 2; mi++)
#pragma unroll
                for (int ni = 0; ni < 8; ni++) {
                    mma16816h(&acc[(mi*8+ni)*4], a1f[mi], &bf[ni>>1][(ni&1)*2]);
                    mma16816h(&acc[(mi*8+ni)*4], a2f[mi], &bf[ni>>1][(ni&1)*2]);
                }
        }
    }

    __syncthreads();
#pragma unroll
    for (int mi = 0; mi < 2; mi++)
#pragma unroll
        for (int ni = 0; ni < 8; ni++) {
            int row = mrow + mi*16 + (lane >> 2);
            int col = ncol + ni*8 + (lane & 3) * 2;
            float* c = &acc[(mi*8+ni)*4];
            Ts[row * TSTR + col]           = c[0];
            Ts[row * TSTR + col + 1]       = c[1];
            Ts[(row + 8) * TSTR + col]     = c[2];
            Ts[(row + 8) * TSTR + col + 1] = c[3];
        }
    __syncthreads();

    const float* adjb = adj + (size_t)b * NN * NN;
    const int a = tid >> 5, c4 = tid & 31;

    // direct tile (jT rows, kT cols): shifted-exp fp16 P + colsum partials
    float cs[4] = {0.f, 0.f, 0.f, 0.f};
#pragma unroll
    for (int it = 0; it < 16; it++) {
        int rr = a + 8 * it;
        int jg = jT * 128 + rr, kg = kT * 128 + 4 * c4;
        float4 av = *(const float4*)&adjb[(size_t)jg * NN + kg];
        const float* tr = &Ts[rr * TSTR + 4 * c4];
        float pv[4];
        pv[0] = (av.x > 0.f) ? __expf(tr[0] - SHIFTC) : 0.f;
        pv[1] = (av.y > 0.f) ? __expf(tr[1] - SHIFTC) : 0.f;
        pv[2] = (av.z > 0.f) ? __expf(tr[2] - SHIFTC) : 0.f;
        pv[3] = (av.w > 0.f) ? __expf(tr[3] - SHIFTC) : 0.f;
        cs[0] += (av.x > 0.f) ? pv[0] : EXPM10;
        cs[1] += (av.y > 0.f) ? pv[1] : EXPM10;
        cs[2] += (av.z > 0.f) ? pv[2] : EXPM10;
        cs[3] += (av.w > 0.f) ? pv[3] : EXPM10;
        __half h4[4];
#pragma unroll
        for (int q = 0; q < 4; q++) h4[q] = __float2half_rn(pv[q]);
        size_t o = (size_t)b * NN * NN + (size_t)jg * NN + kg;
        *(uint2*)&g_P1[o] = *(uint2*)h4;
    }
    *(float4*)&red[a * 128 + 4 * c4] = make_float4(cs[0], cs[1], cs[2], cs[3]);
    __syncthreads();
    if (tid < 128) {
        float s = 0.f;
#pragma unroll
        for (int q = 0; q < 8; q++) s += red[q * 128 + tid];
        g_dpart[(b * 8 + jT) * NN + kT * 128 + tid] = s;
    }
    __syncthreads();

    // mirrored tile (kT rows, jT cols)
    if (jT != kT) {
        float cs2[4] = {0.f, 0.f, 0.f, 0.f};
#pragma unroll
        for (int it = 0; it < 16; it++) {
            int rr = a + 8 * it;
            int kg = kT * 128 + rr, jg = jT * 128 + 4 * c4;
            float4 av = *(const float4*)&adjb[(size_t)kg * NN + jg];
            float e0 = Ts[(4*c4+0) * TSTR + rr];
            float e1 = Ts[(4*c4+1) * TSTR + rr];
            float e2 = Ts[(4*c4+2) * TSTR + rr];
            float e3 = Ts[(4*c4+3) * TSTR + rr];
            float pv[4];
            pv[0] = (av.x > 0.f) ? __expf(e0 - SHIFTC) : 0.f;
            pv[1] = (av.y > 0.f) ? __expf(e1 - SHIFTC) : 0.f;
            pv[2] = (av.z > 0.f) ? __expf(e2 - SHIFTC) : 0.f;
            pv[3] = (av.w > 0.f) ? __expf(e3 - SHIFTC) : 0.f;
            cs2[0] += (av.x > 0.f) ? pv[0] : EXPM10;
            cs2[1] += (av.y > 0.f) ? pv[1] : EXPM10;
            cs2[2] += (av.z > 0.f) ? pv[2] : EXPM10;
            cs2[3] += (av.w > 0.f) ? pv[3] : EXPM10;
            __half h4[4];
#pragma unroll
            for (int q = 0; q < 4; q++) h4[q] = __float2half_rn(pv[q]);
            size_t o = (size_t)b * NN * NN + (size_t)kg * NN + jg;
            *(uint2*)&g_P1[o] = *(uint2*)h4;
        }
        __syncthreads();
        *(float4*)&red[a * 128 + 4 * c4] = make_float4(cs2[0], cs2[1], cs2[2], cs2[3]);
        __syncthreads();
        if (tid < 128) {
            float s = 0.f;
#pragma unroll
            for (int q = 0; q < 8; q++) s += red[q * 128 + tid];
            g_dpart[(b * 8 + kT) * NN + jT * 128 + tid] = s;
        }
    }
}

// ---------------------------------------------------------------------------
// K4: hscale — rden = 1/colsum; hS1 = fp16(rden[j] * h[j][d])
// grid (16 jchunks, 16 b), 256 thr
// ---------------------------------------------------------------------------
__global__ void hscale_kernel() {
    __shared__ float rden[64];
    const int tid = threadIdx.x;
    const int b = blockIdx.y;
    const int j0 = blockIdx.x * 64;
    if (tid < 64) {
        float s = 0.f;
#pragma unroll
        for (int seg = 0; seg < 8; seg++)
            s += g_dpart[(b * 8 + seg) * NN + j0 + tid];
        rden[tid] = 1.0f / s;
    }
    __syncthreads();
#pragma unroll
    for (int it = 0; it < 4; it++) {
        int u = tid + it * 256;              // 1024 units: 128 d x 8 groups of 8 j
        int d = u >> 3, g = u & 7;
        size_t o = ((size_t)(b * DD + d)) * NN + j0 + g * 8;
        float4 va = *(const float4*)&g_hTf[o];
        float4 vb = *(const float4*)&g_hTf[o + 4];
        __half s1[8];
        s1[0] = __float2half_rn(va.x * rden[g*8+0]);
        s1[1] = __float2half_rn(va.y * rden[g*8+1]);
        s1[2] = __float2half_rn(va.z * rden[g*8+2]);
        s1[3] = __float2half_rn(va.w * rden[g*8+3]);
        s1[4] = __float2half_rn(vb.x * rden[g*8+4]);
        s1[5] = __float2half_rn(vb.y * rden[g*8+5]);
        s1[6] = __float2half_rn(vb.z * rden[g*8+6]);
        s1[7] = __float2half_rn(vb.w * rden[g*8+7]);
        *(uint4*)&g_hS1[o] = *(uint4*)s1;
    }
}

// ---------------------------------------------------------------------------
// K5: aggregation — h'[i,d] = sum_j P1[i,j]*hS1[d,j]; SINGLE fp16 product.
// grid (16 iT, 16 b), 2 CTA/SM. Fused gate epilogue.
// ---------------------------------------------------------------------------
#define AG_A1 0
#define AG_B  MATB64
#define AG_SMEM (MATB64 + MATB)   // 27648; epilogue hp 64*132*4 = 33792 -> need 33792
#define AG_SMEM_TOTAL 33792

__global__ void __launch_bounds__(256, 2)
agg_mma_kernel(const float* __restrict__ x,
               const float* __restrict__ wiu, const float* __restrict__ wix,
               const float* __restrict__ wfu, const float* __restrict__ wfx,
               const float* __restrict__ wou, const float* __restrict__ wox,
               float* __restrict__ out) {
    extern __shared__ char smem[];
    const uint32_t sb = smem_u32(smem);
    const int tid = threadIdx.x;
    const int wid = tid >> 5, lane = tid & 31;
    const int b = blockIdx.y;
    const int i0 = blockIdx.x * 64;
    const int mrow = (wid >> 2) * 32, ncol = (wid & 3) * 32;
    const int lg = lane >> 3, lr = lane & 7;

    float acc[32];
#pragma unroll
    for (int i = 0; i < 32; i++) acc[i] = 0.f;

    for (int c = 0; c < 16; c++) {
        const int j0 = c * 64;
        if (c) __syncthreads();
        // A: P1 tile [64 i x 64 j]
#pragma unroll
        for (int it = 0; it < 2; it++) {
            int row = it * 32 + (tid >> 3), f8 = tid & 7;
            size_t so = ((size_t)(b * NN + i0 + row)) * NN + j0 + f8 * 8;
            CP_ASYNC16(sb + AG_A1 + row * (LDO*2) + f8 * 16, (const void*)&g_P1[so]);
        }
        // B: hS1 tile [128 d x 64 j]
#pragma unroll
        for (int it = 0; it < 4; it++) {
            int row = it * 32 + (tid >> 3), f8 = tid & 7;
            size_t so = ((size_t)(b * DD + row)) * NN + j0 + f8 * 8;
            CP_ASYNC16(sb + AG_B + row * (LDO*2) + f8 * 16, (const void*)&g_hS1[so]);
        }
        CP_COMMIT();
        CP_WAIT0();
        __syncthreads();
        // mma: M=64 (mi<2), N=32 per warp, single product
#pragma unroll
        for (int ks = 0; ks < 4; ks++) {
            const int kk = ks * 16;
            uint32_t a1f[2][4];
#pragma unroll
            for (int mi = 0; mi < 2; mi++) {
                uint32_t ro = ((mrow + mi*16 + (lane & 15)) * LDO + kk + (lane >> 4) * 8) * 2;
                ldsm4(a1f[mi], sb + AG_A1 + ro);
            }
            uint32_t bf[2][4];
#pragma unroll
            for (int nb = 0; nb < 2; nb++) {
                int n = ncol + nb * 16 + (lg >> 1) * 8 + lr;
                ldsm4(bf[nb], sb + AG_B + (n * LDO + kk + (lg & 1) * 8) * 2);
            }
#pragma unroll
            for (int mi = 0; mi < 2; mi++)
#pragma unroll
                for (int ni = 0; ni < 4; ni++)
                    mma16816h(&acc[(mi*4+ni)*4], a1f[mi], &bf[ni>>1][(ni&1)*2]);
        }
    }

    // h' = relu(acc) -> hp [64][132]
    __syncthreads();
    float* hp = (float*)smem;
#pragma unroll
    for (int mi = 0; mi < 2; mi++)
#pragma unroll
        for (int ni = 0; ni < 4; ni++) {
            int row = mrow + mi*16 + (lane >> 2);
            int col = ncol + ni*8 + (lane & 3) * 2;
            float* cc = &acc[(mi*4+ni)*4];
            hp[row * 132 + col]         = fmaxf(cc[0], 0.f);
            hp[row * 132 + col + 1]     = fmaxf(cc[1], 0.f);
            hp[(row+8) * 132 + col]     = fmaxf(cc[2], 0.f);
            hp[(row+8) * 132 + col + 1] = fmaxf(cc[3], 0.f);
        }
    __syncthreads();

    float4 ui = *(const float4*)&wiu[lane * 4];
    float4 xi = *(const float4*)&wix[lane * 4];
    float4 uf = *(const float4*)&wfu[lane * 4];
    float4 xf = *(const float4*)&wfx[lane * 4];
    float4 uo = *(const float4*)&wou[lane * 4];
    float4 xo = *(const float4*)&wox[lane * 4];

    for (int r = wid; r < 64; r += 8) {
        size_t n = (size_t)b * NN + i0 + r;
        float4 h4 = *(const float4*)&hp[r * 132 + lane * 4];
        float4 x4 = *(const float4*)&x[n * DD + lane * 4];
        float zi = h4.x*ui.x + h4.y*ui.y + h4.z*ui.z + h4.w*ui.w
                 + x4.x*xi.x + x4.y*xi.y + x4.z*xi.z + x4.w*xi.w;
        float zf = h4.x*uf.x + h4.y*uf.y + h4.z*uf.z + h4.w*uf.w
                 + x4.x*xf.x + x4.y*xf.y + x4.z*xf.z + x4.w*xf.w;
        float zo = h4.x*uo.x + h4.y*uo.y + h4.z*uo.z + h4.w*uo.w
                 + x4.x*xo.x + x4.y*xo.y + x4.z*xo.z + x4.w*xo.w;
#pragma unroll
        for (int off = 16; off; off >>= 1) {
            zi += __shfl_xor_sync(0xffffffffu, zi, off);
            zf += __shfl_xor_sync(0xffffffffu, zf, off);
            zo += __shfl_xor_sync(0xffffffffu, zo, off);
        }
        float ic = 1.f / (1.f + expf(-zi));
        float fc = 1.f / (1.f + expf(-zf));
        float oc = 1.f / (1.f + expf(-zo));
        float4 o;
        o.x = oc * tanhf(ic * h4.x + fc * x4.x);
        o.y = oc * tanhf(ic * h4.y + fc * x4.y);
        o.z = oc * tanhf(ic * h4.z + fc * x4.z);
        o.w = oc * tanhf(ic * h4.w + fc * x4.w);
        *(float4*)&out[n * DD + lane * 4] = o;
    }
}

// ---------------------------------------------------------------------------
extern "C" void kernel_launch(void* const* d_in, const int* in_sizes, int n_in,
                              void* d_out, int out_size) {
    const float* x   = (const float*)d_in[0];
    const float* adj = (const float*)d_in[1];
    const float* Ww  = (const float*)d_in[2];
    const float* Wb  = (const float*)d_in[3];
    const float* A   = (const float*)d_in[4];
    const float* wiu = (const float*)d_in[5];
    const float* wix = (const float*)d_in[6];
    const float* wfu = (const float*)d_in[7];
    const float* wfx = (const float*)d_in[8];
    const float* wou = (const float*)d_in[9];
    const float* wox = (const float*)d_in[10];
    float* out = (float*)d_out;

    cudaFuncSetAttribute((const void*)gemmht_kernel,
                         cudaFuncAttributeMaxDynamicSharedMemorySize, 131072);
    cudaFuncSetAttribute((const void*)scores_mma_kernel,
                         cudaFuncAttributeMaxDynamicSharedMemorySize, SC_SMEM);
    cudaFuncSetAttribute((const void*)agg_mma_kernel,
                         cudaFuncAttributeMaxDynamicSharedMemorySize, AG_SMEM_TOTAL);

    prep_M2_kernel<<<16, 256>>>(Ww, Wb, A);
    gemmht_kernel<<<dim3(128, 2), 256, 131072>>>(x, Ww, Wb);
    scores_mma_kernel<<<dim3(36, 16), 256, SC_SMEM>>>(adj);
    hscale_kernel<<<dim3(16, 16), 256>>>();
    agg_mma_kernel<<<dim3(16, 16), 256, AG_SMEM_TOTAL>>>(x, wiu, wix, wfu, wfx, wou, wox, out);
}